// round 14
// baseline (speedup 1.0000x reference)
#include <cuda_runtime.h>
#include <cuda_bf16.h>
#include <cstdint>

#define SS 256
#define BATCH 2
#define HIDN 512
#define NHEAD 8
#define HDIM 64
#define NTOK 512
#define EPSF 1e-15f
#define CLIP1 0.9999999f
#define MAXNORM 0.996f
#define NSPLIT 4

// ---------------- device scratch ----------------
__device__ __align__(256) float g_mx[3 * NTOK * HIDN];
__device__ __align__(256) __nv_bfloat16 g_xhi[NTOK * HIDN];
__device__ __align__(256) __nv_bfloat16 g_xlo[NTOK * HIDN];
__device__ __align__(256) __nv_bfloat16 g_whi[3 * HIDN * HIDN];
__device__ __align__(256) __nv_bfloat16 g_wlo[3 * HIDN * HIDN];
__device__ __align__(256) float g_q[BATCH * NHEAD * SS * HDIM];
__device__ __align__(256) float g_k[BATCH * NHEAD * SS * HDIM];
__device__ __align__(256) float g_gv[BATCH * NHEAD * SS * HDIM];
__device__ __align__(256) float g_x2[BATCH * NHEAD * SS];
__device__ __align__(256) float g_y2[BATCH * NHEAD * SS];
__device__ __align__(256) float g_gm1[BATCH * NHEAD * SS];
__device__ __align__(256) float g_probs[BATCH * NHEAD * SS * SS];  // fallback
__device__ __align__(256) float g_nomp[NSPLIT][BATCH * NHEAD * SS * HDIM];

static __device__ __forceinline__ float frcp(float x) {
    float r; asm("rcp.approx.f32 %0, %1;" : "=f"(r) : "f"(x)); return r;
}
static __device__ __forceinline__ float frsq(float x) {
    float r; asm("rsqrt.approx.f32 %0, %1;" : "=f"(r) : "f"(x)); return r;
}
static __device__ __forceinline__ uint32_t smem_to_u32(const void* p) {
    uint32_t a;
    asm("{ .reg .u64 t; cvta.to.shared.u64 t, %1; cvt.u32.u64 %0, t; }" : "=r"(a) : "l"(p));
    return a;
}

#define LDSM4(r, a) \
    asm volatile("ldmatrix.sync.aligned.m8n8.x4.shared.b16 {%0,%1,%2,%3}, [%4];" \
                 : "=r"((r)[0]), "=r"((r)[1]), "=r"((r)[2]), "=r"((r)[3]) : "r"(a))

#define MMA16816(dd, a, b0, b1) \
    asm volatile("mma.sync.aligned.m16n8k16.row.col.f32.bf16.bf16.f32 " \
                 "{%0,%1,%2,%3}, {%4,%5,%6,%7}, {%8,%9}, {%0,%1,%2,%3};" \
                 : "+f"((dd)[0]), "+f"((dd)[1]), "+f"((dd)[2]), "+f"((dd)[3]) \
                 : "r"((a)[0]), "r"((a)[1]), "r"((a)[2]), "r"((a)[3]), \
                   "r"(b0), "r"(b1))

template <int K>
static __device__ __forceinline__ void bredK(float* vals, float* sh) {
    int lane = threadIdx.x & 31, wid = threadIdx.x >> 5;
#pragma unroll
    for (int j = 0; j < K; j++) {
        float v = vals[j];
#pragma unroll
        for (int o = 16; o > 0; o >>= 1) v += __shfl_xor_sync(0xffffffffu, v, o);
        if (lane == 0) sh[j * 16 + wid] = v;
    }
    __syncthreads();
#pragma unroll
    for (int j = 0; j < K; j++) {
        float t = 0.f;
#pragma unroll
        for (int i = 0; i < 16; i++) t += sh[j * 16 + i];
        vals[j] = t;
    }
}

// ---------------- kernel 0: fp32 -> bf16 hi/lo split ----------------
__global__ __launch_bounds__(512) void k_convert(const float* __restrict__ X,
                                                 const float* __restrict__ Wq,
                                                 const float* __restrict__ Wk,
                                                 const float* __restrict__ Wv) {
    int stride = gridDim.x * blockDim.x;
    for (int i = blockIdx.x * blockDim.x + threadIdx.x; i < 4 * 262144; i += stride) {
        int sel = i >> 18, off = i & 262143;
        const float* src = (sel == 0) ? X : ((sel == 1) ? Wq : ((sel == 2) ? Wk : Wv));
        float v = src[off];
        __nv_bfloat16 hi = __float2bfloat16(v);
        __nv_bfloat16 lo = __float2bfloat16(v - __bfloat162float(hi));
        if (sel == 0) { g_xhi[off] = hi; g_xlo[off] = lo; }
        else {
            int wo = (sel - 1) * 262144 + off;
            g_whi[wo] = hi; g_wlo[wo] = lo;
        }
    }
}

// ---------------- kernel 1: bf16-split HMMA GEMM ----------------
__global__ __launch_bounds__(256) void k_gemm_mma() {
    extern __shared__ __align__(1024) char smem[];
    int tid = threadIdx.x;
    int w = tid >> 5, lane = tid & 31;
    int n0 = blockIdx.x * 64, m0 = blockIdx.y * 64, p = blockIdx.z;
    int wm = w & 3, wn = w >> 2;
    uint32_t sb32 = smem_to_u32(smem);

    const uint4* xhi4 = (const uint4*)g_xhi;
    const uint4* xlo4 = (const uint4*)g_xlo;
    const uint4* whi4 = (const uint4*)g_whi;
    const uint4* wlo4 = (const uint4*)g_wlo;

    float d[4][4];
#pragma unroll
    for (int c = 0; c < 4; c++)
#pragma unroll
        for (int j = 0; j < 4; j++) d[c][j] = 0.f;

    auto stage = [&](int ch, int bc) {
        char* sb = smem + bc * 32768;
#pragma unroll
        for (int it = 0; it < 8; it++) {
            int i = tid + it * 256;
            int a = (i >> 9) & 1;
            int idx = i & 511;
            int r = idx >> 3, u = idx & 7;
            uint4 v; uint32_t dst;
            if (i < 1024) {
                v = (a ? xlo4 : xhi4)[(m0 + r) * 64 + ch * 8 + u];
                dst = a * 8192 + r * 128 + ((u ^ (r & 7)) << 4);
            } else {
                v = (a ? wlo4 : whi4)[p * 32768 + (n0 + r) * 64 + ch * 8 + u];
                dst = 16384 + a * 8192 + r * 128 + ((u ^ (r & 7)) << 4);
            }
            *(uint4*)(sb + dst) = v;
        }
    };

    stage(0, 0);
    __syncthreads();

#pragma unroll 1
    for (int ch = 0; ch < 8; ch++) {
        int bc = ch & 1;
        if (ch + 1 < 8) stage(ch + 1, 1 - bc);

        uint32_t abase = sb32 + bc * 32768;
        uint32_t bbase = abase + 16384;

        int ar = wm * 16 + (lane & 15);
        int asel = lane >> 4;
        int bsel = lane >> 4;
        int nkh = (lane >> 3) & 1;
        int nrl = lane & 7;

#pragma unroll
        for (int kk = 0; kk < 4; kk++) {
            int ub = kk * 2;
            uint32_t ah[4], al[4];
            {
                int au = ub + asel;
                uint32_t aaddr = abase + ar * 128 + ((au ^ (ar & 7)) << 4);
                LDSM4(ah, aaddr);
                LDSM4(al, aaddr + 8192);
            }
#pragma unroll
            for (int cp = 0; cp < 2; cp++) {
                int cc = cp * 2 + bsel;
                int nr = wn * 32 + cc * 8 + nrl;
                int bu = ub + nkh;
                uint32_t baddr = bbase + nr * 128 + ((bu ^ (nr & 7)) << 4);
                uint32_t bh[4], bl[4];
                LDSM4(bh, baddr);
                LDSM4(bl, baddr + 8192);
                MMA16816(d[2 * cp],     ah, bh[0], bh[1]);
                MMA16816(d[2 * cp + 1], ah, bh[2], bh[3]);
                MMA16816(d[2 * cp],     ah, bl[0], bl[1]);
                MMA16816(d[2 * cp + 1], ah, bl[2], bl[3]);
                MMA16816(d[2 * cp],     al, bh[0], bh[1]);
                MMA16816(d[2 * cp + 1], al, bh[2], bh[3]);
            }
        }
        __syncthreads();
    }

    float* out = g_mx + p * (NTOK * HIDN);
    int g = lane >> 2, c2 = (lane & 3) * 2;
    int row = m0 + wm * 16 + g;
#pragma unroll
    for (int c = 0; c < 4; c++) {
        int col = n0 + wn * 32 + c * 8 + c2;
        *(float2*)(out + row * 512 + col) = make_float2(d[c][0], d[c][1]);
        *(float2*)(out + (row + 8) * 512 + col) = make_float2(d[c][2], d[c][3]);
    }
}

// ---------------- kernel 2: per-token manifold nonlinearity ----------------
__global__ __launch_bounds__(512) void k_token(const float* __restrict__ query,
                                               const float* __restrict__ bq,
                                               const float* __restrict__ bk,
                                               const float* __restrict__ bv) {
    __shared__ float sh[48];
    int tt = blockIdx.x, p = blockIdx.y, c = threadIdx.x;
    const float* bias = (p == 0) ? bq : ((p == 1) ? bk : bv);

    float x  = query[tt * 512 + c];
    float mx = g_mx[p * (NTOK * HIDN) + tt * 512 + c];
    float bb = bias[c];

    float r3[3] = {x * x, mx * mx, bb * bb};
    bredK<3>(r3, sh);
    __syncthreads();

    float xn = fmaxf(sqrtf(r3[0]), EPSF);
    float mn = fmaxf(sqrtf(r3[1]), EPSF);
    float b2 = r3[2];
    float sc = tanhf(mn / xn * atanhf(fminf(xn, CLIP1))) / mn;
    float res = sc * mx;

    float r2[2] = {res * bb, res * res};
    bredK<2>(r2, sh);
    __syncthreads();
    float rb = r2[0], rr = r2[1];

    float A  = 1.f + 2.f * rb + b2;
    float Bc = 1.f - rr;
    float den = fmaxf(1.f + 2.f * rb + rr * b2, EPSF);
    float y = (A * res + Bc * bb) / den;

    float r1[1] = {y * y};
    bredK<1>(r1, sh);
    __syncthreads();
    float n = fmaxf(sqrtf(r1[0]), EPSF);
    if (n > MAXNORM) { y *= MAXNORM / n; n = MAXNORM; }

    float lf = atanhf(fminf(n, CLIP1)) / n;
    float u = lf * y;

    float uu = u * u;
#pragma unroll
    for (int o = 16; o > 0; o >>= 1) uu += __shfl_xor_sync(0xffffffffu, uu, o);
    int lane = c & 31, wid = c >> 5;
    if (lane == 0) sh[wid] = uu;
    __syncthreads();
    int chunk = c >> 6;
    float cs = sh[chunk * 2] + sh[chunk * 2 + 1];
    float n64 = fmaxf(sqrtf(cs), EPSF);
    float t = tanhf(n64);
    float e = t / n64 * u;

    int s = tt >> 1, b = tt & 1;
    int h = s >> 5, s2 = ((s & 31) << 3) | chunk, d = c & 63;
    int hidx = (b * NHEAD + h) * SS + s2;
    int idx = hidx * 64 + d;
    if (p == 0) {
        g_q[idx] = e;
        if (d == 0) g_x2[hidx] = t * t;
    } else if (p == 1) {
        g_k[idx] = e;
        if (d == 0) g_y2[hidx] = t * t;
    } else {
        float gamma = 2.f / fmaxf(1.f - t * t, EPSF);
        g_gv[idx] = gamma * e;
        if (d == 0) g_gm1[hidx] = gamma - 1.f;
    }
}

// ---------------- kernel 3: pairwise scores -> probs (half-dim split) ----------------
// grid (16 qtiles, 8 heads, 2 batch) = 256 blocks, block 256.
// Thread = (q 0..15 = tid>>4, nset 0..7 = (tid>>1)&7, half = tid&1).
// Each thread handles 32 dims of each (q,n) pair; partner lane (lane^1) has the
// other 32 dims; combine via shfl. xq payload: 8 float4 = 32 regs.
__global__ __launch_bounds__(256, 2) void k_scores(float* __restrict__ probs) {
    extern __shared__ float sm[];
    float* s_kl = sm;               // 256 * 17 float4
    float* s_y2 = sm + 256 * 68;    // 256
    int b = blockIdx.z, h = blockIdx.y, qt = blockIdx.x;
    int bh = b * NHEAD + h;
    int tid = threadIdx.x;

    const float4* gk4 = (const float4*)(g_k) + bh * SS * 16;
    float4* skl4 = (float4*)s_kl;
    for (int i = tid; i < SS * 16; i += 256) {
        int n = i >> 4, d4 = i & 15;
        skl4[n * 17 + d4] = gk4[i];
    }
    for (int i = tid; i < SS; i += 256) s_y2[i] = g_y2[bh * SS + i];
    __syncthreads();

    int q = qt * 16 + (tid >> 4);
    int nset = (tid >> 1) & 7;
    int half = tid & 1;

    // this thread's 32 dims: float4 indices half*8 .. half*8+7
    float4 xq[8];
    const float4* gq4 = (const float4*)(g_q) + (bh * SS + q) * 16 + half * 8;
#pragma unroll
    for (int i = 0; i < 8; i++) xq[i] = gq4[i];
    float x2 = g_x2[bh * SS + q];
    float Bc = 1.f - x2;

    float* pg = probs + (bh * SS + q) * SS;

#pragma unroll 1
    for (int j = 0; j < 32; j++) {
        int n = nset + (j << 3);
        const float4* kr = skl4 + n * 17 + half * 8;

        // pass 1: partial dot over my 32 dims
        float a0 = 0.f, a1 = 0.f, a2 = 0.f, a3 = 0.f;
#pragma unroll
        for (int i = 0; i < 8; i++) {
            float4 kv = kr[i];
            a0 = fmaf(xq[i].x, kv.x, a0);
            a1 = fmaf(xq[i].y, kv.y, a1);
            a2 = fmaf(xq[i].z, kv.z, a2);
            a3 = fmaf(xq[i].w, kv.w, a3);
        }
        float ap = (a0 + a1) + (a2 + a3);
        float xy = -(ap + __shfl_xor_sync(0xffffffffu, ap, 1));

        float y2 = s_y2[n];
        float base = fmaf(2.f, xy, 1.f);
        float A = base + y2;
        float den = fmaxf(fmaf(x2, y2, base), EPSF);
        float Aiv = A * frcp(den);
        float r = -Bc * frcp(A);

        // pass 2: partial sum of 1/e^2 over my 32 dims, e = xq + r*kl
        float s0 = 0.f, s1 = 0.f, s2 = 0.f, s3 = 0.f;
#pragma unroll
        for (int i = 0; i < 8; i++) {
            float4 kv = kr[i];
            float e0 = fmaf(r, kv.x, xq[i].x);
            float e1 = fmaf(r, kv.y, xq[i].y);
            float e2 = fmaf(r, kv.z, xq[i].z);
            float e3 = fmaf(r, kv.w, xq[i].w);
            s0 += frcp(e0 * e0);
            s1 += frcp(e1 * e1);
            s2 += frcp(e2 * e2);
            s3 += frcp(e3 * e3);
        }
        float sp = (s0 + s1) + (s2 + s3);
        float stot = sp + __shfl_xor_sync(0xffffffffu, sp, 1);
        if (half == 0) {
            float t1 = Aiv * frsq(stot);
            pg[n] = 0.5f * (1.f - fminf(t1, CLIP1));
        }
    }
}

// ---------------- kernel 4: n-split midpoint GEMM, register-tiled ----------------
__global__ __launch_bounds__(256) void k_mid(const float* __restrict__ probs) {
    extern __shared__ float sm[];
    float* s_p = sm;
    float4* s_gv4 = (float4*)(sm + 64 * 132);
    int qh = blockIdx.x, bh = blockIdx.y, ns = blockIdx.z;
    int tid = threadIdx.x;
    int q0 = qh * 128, n0 = ns * 64;

    const float4* gp4 = (const float4*)probs;
#pragma unroll
    for (int it = 0; it < 8; it++) {
        int i = tid + it * 256;
        int q = i >> 4, n4 = i & 15;
        float4 v = gp4[(bh * SS + q0 + q) * 64 + (n0 >> 2) + n4];
        s_p[(n4 * 4 + 0) * 132 + q] = v.x;
        s_p[(n4 * 4 + 1) * 132 + q] = v.y;
        s_p[(n4 * 4 + 2) * 132 + q] = v.z;
        s_p[(n4 * 4 + 3) * 132 + q] = v.w;
    }
    const float4* gg4 = (const float4*)(g_gv) + bh * SS * 16;
#pragma unroll
    for (int it = 0; it < 4; it++) {
        int i = tid + it * 256;
        int n = i >> 4, d4 = i & 15;
        s_gv4[n * 17 + d4] = gg4[(n0 + n) * 16 + d4];
    }
    __syncthreads();

    int qg = tid >> 4, d4 = tid & 15;
    float acc[8][4];
#pragma unroll
    for (int i = 0; i < 8; i++)
#pragma unroll
        for (int j = 0; j < 4; j++) acc[i][j] = 0.f;

#pragma unroll 4
    for (int n = 0; n < 64; n++) {
        float4 gv = s_gv4[n * 17 + d4];
        float4 pa = *(const float4*)(s_p + n * 132 + qg * 8);
        float4 pb = *(const float4*)(s_p + n * 132 + qg * 8 + 4);
        acc[0][0] = fmaf(pa.x, gv.x, acc[0][0]); acc[0][1] = fmaf(pa.x, gv.y, acc[0][1]);
        acc[0][2] = fmaf(pa.x, gv.z, acc[0][2]); acc[0][3] = fmaf(pa.x, gv.w, acc[0][3]);
        acc[1][0] = fmaf(pa.y, gv.x, acc[1][0]); acc[1][1] = fmaf(pa.y, gv.y, acc[1][1]);
        acc[1][2] = fmaf(pa.y, gv.z, acc[1][2]); acc[1][3] = fmaf(pa.y, gv.w, acc[1][3]);
        acc[2][0] = fmaf(pa.z, gv.x, acc[2][0]); acc[2][1] = fmaf(pa.z, gv.y, acc[2][1]);
        acc[2][2] = fmaf(pa.z, gv.z, acc[2][2]); acc[2][3] = fmaf(pa.z, gv.w, acc[2][3]);
        acc[3][0] = fmaf(pa.w, gv.x, acc[3][0]); acc[3][1] = fmaf(pa.w, gv.y, acc[3][1]);
        acc[3][2] = fmaf(pa.w, gv.z, acc[3][2]); acc[3][3] = fmaf(pa.w, gv.w, acc[3][3]);
        acc[4][0] = fmaf(pb.x, gv.x, acc[4][0]); acc[4][1] = fmaf(pb.x, gv.y, acc[4][1]);
        acc[4][2] = fmaf(pb.x, gv.z, acc[4][2]); acc[4][3] = fmaf(pb.x, gv.w, acc[4][3]);
        acc[5][0] = fmaf(pb.y, gv.x, acc[5][0]); acc[5][1] = fmaf(pb.y, gv.y, acc[5][1]);
        acc[5][2] = fmaf(pb.y, gv.z, acc[5][2]); acc[5][3] = fmaf(pb.y, gv.w, acc[5][3]);
        acc[6][0] = fmaf(pb.z, gv.x, acc[6][0]); acc[6][1] = fmaf(pb.z, gv.y, acc[6][1]);
        acc[6][2] = fmaf(pb.z, gv.z, acc[6][2]); acc[6][3] = fmaf(pb.z, gv.w, acc[6][3]);
        acc[7][0] = fmaf(pb.w, gv.x, acc[7][0]); acc[7][1] = fmaf(pb.w, gv.y, acc[7][1]);
        acc[7][2] = fmaf(pb.w, gv.z, acc[7][2]); acc[7][3] = fmaf(pb.w, gv.w, acc[7][3]);
    }
    float* outp = g_nomp[ns];
#pragma unroll
    for (int i = 0; i < 8; i++) {
        int row = bh * SS + q0 + qg * 8 + i;
        *(float4*)(outp + row * 64 + d4 * 4) =
            make_float4(acc[i][0], acc[i][1], acc[i][2], acc[i][3]);
    }
}

// ---------------- kernel 5: den + epilogue + expmap0 + transpose ----------------
__global__ __launch_bounds__(512) void k_final(float* __restrict__ out,
                                               const float* __restrict__ probs) {
    __shared__ float shd[16], shn[16], shu[16];
    int t = blockIdx.x;
    int b = t >> 8, q = t & 255;
    int c = threadIdx.x;
    int h = c >> 6, d = c & 63;
    int bh = b * NHEAD + h;
    int row = bh * SS + q;
    int lane = c & 31, wid = c >> 5;

    float4 pv = ((const float4*)probs)[row * 64 + d];
    float4 g1 = ((const float4*)g_gm1)[bh * 64 + d];
    float ad = pv.x * g1.x + pv.y * g1.y + pv.z * g1.z + pv.w * g1.w;
#pragma unroll
    for (int o = 16; o > 0; o >>= 1) ad += __shfl_xor_sync(0xffffffffu, ad, o);
    if (lane == 0) shd[wid] = ad;
    __syncthreads();
    float dn0 = shd[h * 2] + shd[h * 2 + 1];
    float dn = fmaxf(fabsf(dn0), 1e-10f);
    if (dn0 < 0.f) dn = -dn;

    int nidx = row * 64 + d;
    float m = g_nomp[0][nidx] + g_nomp[1][nidx] + g_nomp[2][nidx] + g_nomp[3][nidx];
    m = m / dn;

    float nn = m * m;
#pragma unroll
    for (int o = 16; o > 0; o >>= 1) nn += __shfl_xor_sync(0xffffffffu, nn, o);
    if (lane == 0) shn[wid] = nn;
    __syncthreads();
    float nm = fmaxf(sqrtf(shn[h * 2] + shn[h * 2 + 1]), EPSF);
    float f = 0.5f * atanhf(fminf(nm, CLIP1)) / nm;
    float u = f * m;

    float uu = u * u;
#pragma unroll
    for (int o = 16; o > 0; o >>= 1) uu += __shfl_xor_sync(0xffffffffu, uu, o);
    if (lane == 0) shu[wid] = uu;
    __syncthreads();
    float tot = 0.f;
#pragma unroll
    for (int i = 0; i < 16; i++) tot += shu[i];
    float n = fmaxf(sqrtf(tot), EPSF);
    float f2 = tanhf(n) / n;
    out[(q * BATCH + b) * HIDN + c] = f2 * u;
}

// ---------------- launch ----------------
extern "C" void kernel_launch(void* const* d_in, const int* in_sizes, int n_in,
                              void* d_out, int out_size) {
    const float* query = (const float*)d_in[0];
    const float* Wq = (const float*)d_in[1];
    const float* bq = (const float*)d_in[2];
    const float* Wk = (const float*)d_in[3];
    const float* bk = (const float*)d_in[4];
    const float* Wv = (const float*)d_in[5];
    const float* bv = (const float*)d_in[6];
    float* out = (float*)d_out;

    const int CTXN = SS * BATCH * HIDN;      // 262144
    const int PRN = BATCH * NHEAD * SS * SS; // 1048576
    float* dctx = 0;
    float* dpro = 0;
    if (out_size >= CTXN + PRN) { dctx = out; dpro = out + CTXN; }
    else if (out_size == PRN)   { dpro = out; }
    else                        { dctx = out; }

    const int SMEM_MMA    = 65536;
    const int SMEM_SCORES = (256 * 68 + 256) * 4;           // 70656
    const int SMEM_MID    = (64 * 132 + 64 * 68) * 4;       // 51200
    cudaFuncSetAttribute(k_gemm_mma, cudaFuncAttributeMaxDynamicSharedMemorySize, SMEM_MMA);
    cudaFuncSetAttribute(k_scores,   cudaFuncAttributeMaxDynamicSharedMemorySize, SMEM_SCORES);
    cudaFuncSetAttribute(k_mid,      cudaFuncAttributeMaxDynamicSharedMemorySize, SMEM_MID);

    k_convert<<<512, 512>>>(query, Wq, Wk, Wv);
    k_gemm_mma<<<dim3(8, 8, 3), 256, SMEM_MMA>>>();
    k_token<<<dim3(512, 3), 512>>>(query, bq, bk, bv);

    float* probs_ptr = dpro;
    if (!probs_ptr) cudaGetSymbolAddress((void**)&probs_ptr, g_probs);

    k_scores<<<dim3(16, 8, 2), 256, SMEM_SCORES>>>(probs_ptr);
    if (dctx) {
        k_mid<<<dim3(2, 16, NSPLIT), 256, SMEM_MID>>>(probs_ptr);
        k_final<<<512, 512>>>(dctx, probs_ptr);
    }
}